// round 3
// baseline (speedup 1.0000x reference)
#include <cuda_runtime.h>

#define NUM_USERS 100000
#define NUM_ITEMS 50000
#define N_NODES   150000
#define DIM       64
#define NNZ       4800000
#define NEG_SLOPE 0.01f

// Persistent scratch (allocation-free rule: __device__ globals).
__device__ float g_ego[(size_t)N_NODES * DIM];   // 38.4 MB
__device__ float g_side[(size_t)N_NODES * DIM];  // 38.4 MB

// ---------------------------------------------------------------------------
// Init: ego = concat(user_emb, item_emb); also writes output column block 0.
// One thread per float4: 150000*16 threads (exact grid).
// ---------------------------------------------------------------------------
__global__ void init_kernel(const float* __restrict__ ue,
                            const float* __restrict__ ie,
                            float* __restrict__ out) {
    int i = blockIdx.x * 256 + threadIdx.x;   // 0 .. N_NODES*16-1
    int node = i >> 4;
    int q    = i & 15;
    const float4* src = (node < NUM_USERS)
        ? (const float4*)(ue + (size_t)node * DIM)
        : (const float4*)(ie + (size_t)(node - NUM_USERS) * DIM);
    float4 v = src[q];
    ((float4*)(g_ego + (size_t)node * DIM))[q] = v;
    ((float4*)(out  + (size_t)node * 256))[q]  = v;
}

// ---------------------------------------------------------------------------
// Zero the scatter target. 2.4M float4 stores (exact grid).
// ---------------------------------------------------------------------------
__global__ void zero_kernel() {
    int i = blockIdx.x * 256 + threadIdx.x;
    ((float4*)g_side)[i] = make_float4(0.f, 0.f, 0.f, 0.f);
}

// ---------------------------------------------------------------------------
// SpMM: side[row] += val * ego[col] for each edge.
// 16 threads per edge, one float4 each -> a gather instruction covers 4 full
// 128B lines of one embedding row. Edge metadata loaded once per 16-thread
// group (lanes 0/16 of each warp) and broadcast via shfl, streamed with
// evict-first hint so it doesn't evict L2-resident ego/side.
// Scatter via vector reduction (red.global.add.v4.f32, sm_90+).
// ---------------------------------------------------------------------------
__global__ void spmm_kernel(const int*   __restrict__ rows,
                            const int*   __restrict__ cols,
                            const float* __restrict__ vals) {
    long long tid = (long long)blockIdx.x * 256 + threadIdx.x;
    int e = (int)(tid >> 4);
    int q = (int)(tid & 15);
    int lane = threadIdx.x & 31;

    // Two edges per warp: lanes 0-15 handle edge e(group0), lanes 16-31
    // edge e(group1). Lane 0 / lane 16 load their edge's metadata.
    int r = 0, c = 0; float v = 0.f;
    if ((lane & 15) == 0) {
        r = __ldcs(rows + e);
        c = __ldcs(cols + e);
        v = __ldcs(vals + e);
    }
    int src = lane & 16;                 // 0 or 16
    r = __shfl_sync(0xffffffffu, r, src);
    c = __shfl_sync(0xffffffffu, c, src);
    v = __shfl_sync(0xffffffffu, v, src);

    float4 x = ((const float4*)(g_ego + (size_t)c * DIM))[q];
    float4* dst = ((float4*)(g_side + (size_t)r * DIM)) + q;
#if defined(__CUDA_ARCH__) && (__CUDA_ARCH__ >= 900)
    asm volatile("red.global.add.v4.f32 [%0], {%1, %2, %3, %4};"
                 :: "l"(dst), "f"(v * x.x), "f"(v * x.y),
                    "f"(v * x.z), "f"(v * x.w)
                 : "memory");
#else
    float* d = (float*)dst;
    atomicAdd(d + 0, v * x.x);
    atomicAdd(d + 1, v * x.y);
    atomicAdd(d + 2, v * x.z);
    atomicAdd(d + 3, v * x.w);
#endif
}

// ---------------------------------------------------------------------------
// Transform: ego = leaky_relu(side @ gc_w^T + gc_b);
//            out_block = ego @ bi_w^T + bi_b; g_ego updated in place.
// Block = 256 threads = 8 warps. Thread owns one output o (0..63) for a
// 4-node group g (0..3) -> 16 nodes per block iteration.
// Weights in shared, padded to 68 floats/row (conflict-free LDS.128 across o).
// side/ego tiles stored k-major transposed as float4-of-nodes so the per-k
// node vector is one broadcast LDS.128.
// ---------------------------------------------------------------------------
__global__ __launch_bounds__(256) void transform_kernel(
    const float* __restrict__ gcw, const float* __restrict__ gcb,
    const float* __restrict__ biw, const float* __restrict__ bib,
    float* __restrict__ out, int outcol)
{
    __shared__ __align__(16) float wgc[64][68];
    __shared__ __align__(16) float wbi[64][68];
    __shared__ float bgc[64];
    __shared__ float bbi[64];
    __shared__ float4 sT[64][5];  // [k][node_group], 16 nodes + 1 f4 pad
    __shared__ float4 eT[64][5];

    int tx = threadIdx.x;
    for (int i = tx; i < 64 * 64; i += 256) {
        int o = i >> 6, k = i & 63;
        wgc[o][k] = gcw[i];
        wbi[o][k] = biw[i];
    }
    if (tx < 64) { bgc[tx] = gcb[tx]; bbi[tx] = bib[tx]; }

    int warp = tx >> 5, lane = tx & 31;
    int o = ((warp & 1) << 5) | lane;   // output index 0..63
    int g = warp >> 1;                  // node group 0..3
    float* sTf = (float*)sT;            // scalar view, stride 20 per k
    float* eTf = (float*)eT;
    __syncthreads();

    for (int n0 = blockIdx.x * 16; n0 < N_NODES; n0 += gridDim.x * 16) {
        // Stage side tile transposed: sT[k][nl]
        #pragma unroll
        for (int j = 0; j < 4; j++) {
            int idx = tx + j * 256;
            int nl = idx >> 6, k = idx & 63;
            sTf[k * 20 + nl] = g_side[(size_t)(n0 + nl) * DIM + k];
        }
        __syncthreads();

        // Phase A: gc matmul + bias + leaky relu
        float a0 = bgc[o], a1 = a0, a2 = a0, a3 = a0;
        #pragma unroll
        for (int k4 = 0; k4 < 16; k4++) {
            float4 w  = *(const float4*)(&wgc[o][k4 * 4]);
            float4 sA = sT[k4 * 4 + 0][g];
            float4 sB = sT[k4 * 4 + 1][g];
            float4 sC = sT[k4 * 4 + 2][g];
            float4 sD = sT[k4 * 4 + 3][g];
            a0 += w.x * sA.x + w.y * sB.x + w.z * sC.x + w.w * sD.x;
            a1 += w.x * sA.y + w.y * sB.y + w.z * sC.y + w.w * sD.y;
            a2 += w.x * sA.z + w.y * sB.z + w.z * sC.z + w.w * sD.z;
            a3 += w.x * sA.w + w.y * sB.w + w.z * sC.w + w.w * sD.w;
        }
        a0 = a0 > 0.f ? a0 : NEG_SLOPE * a0;
        a1 = a1 > 0.f ? a1 : NEG_SLOPE * a1;
        a2 = a2 > 0.f ? a2 : NEG_SLOPE * a2;
        a3 = a3 > 0.f ? a3 : NEG_SLOPE * a3;

        int nb = n0 + (g << 2);
        g_ego[(size_t)(nb + 0) * DIM + o] = a0;
        g_ego[(size_t)(nb + 1) * DIM + o] = a1;
        g_ego[(size_t)(nb + 2) * DIM + o] = a2;
        g_ego[(size_t)(nb + 3) * DIM + o] = a3;
        eTf[o * 20 + (g << 2) + 0] = a0;
        eTf[o * 20 + (g << 2) + 1] = a1;
        eTf[o * 20 + (g << 2) + 2] = a2;
        eTf[o * 20 + (g << 2) + 3] = a3;
        __syncthreads();

        // Phase B: bi matmul + bias -> output block
        float b0 = bbi[o], b1 = b0, b2 = b0, b3 = b0;
        #pragma unroll
        for (int k4 = 0; k4 < 16; k4++) {
            float4 w  = *(const float4*)(&wbi[o][k4 * 4]);
            float4 eA = eT[k4 * 4 + 0][g];
            float4 eB = eT[k4 * 4 + 1][g];
            float4 eC = eT[k4 * 4 + 2][g];
            float4 eD = eT[k4 * 4 + 3][g];
            b0 += w.x * eA.x + w.y * eB.x + w.z * eC.x + w.w * eD.x;
            b1 += w.x * eA.y + w.y * eB.y + w.z * eC.y + w.w * eD.y;
            b2 += w.x * eA.z + w.y * eB.z + w.z * eC.z + w.w * eD.z;
            b3 += w.x * eA.w + w.y * eB.w + w.z * eC.w + w.w * eD.w;
        }
        out[(size_t)(nb + 0) * 256 + outcol + o] = b0;
        out[(size_t)(nb + 1) * 256 + outcol + o] = b1;
        out[(size_t)(nb + 2) * 256 + outcol + o] = b2;
        out[(size_t)(nb + 3) * 256 + outcol + o] = b3;
        __syncthreads();   // protect sT/eT for next iteration
    }
}

// ---------------------------------------------------------------------------
extern "C" void kernel_launch(void* const* d_in, const int* in_sizes, int n_in,
                              void* d_out, int out_size) {
    const float* user_emb = (const float*)d_in[0];
    const float* item_emb = (const float*)d_in[1];
    const float* gc_w     = (const float*)d_in[2];  // [3,64,64]
    const float* gc_b     = (const float*)d_in[3];  // [3,64]
    const float* bi_w     = (const float*)d_in[4];
    const float* bi_b     = (const float*)d_in[5];
    const int*   rows     = (const int*)d_in[6];
    const int*   cols     = (const int*)d_in[7];
    const float* vals     = (const float*)d_in[8];
    float* out = (float*)d_out;

    // ego init + output column block 0
    init_kernel<<<(N_NODES * 16) / 256, 256>>>(user_emb, item_emb, out);

    for (int l = 0; l < 3; l++) {
        zero_kernel<<<(N_NODES * DIM / 4) / 256, 256>>>();
        spmm_kernel<<<(int)(((long long)NNZ * 16) / 256), 256>>>(rows, cols, vals);
        transform_kernel<<<1480, 256>>>(gc_w + (size_t)l * DIM * DIM,
                                        gc_b + (size_t)l * DIM,
                                        bi_w + (size_t)l * DIM * DIM,
                                        bi_b + (size_t)l * DIM,
                                        out, DIM * (l + 1));
    }
}

// round 10
// speedup vs baseline: 1.4895x; 1.4895x over previous
#include <cuda_runtime.h>

#define NUM_USERS 100000
#define NUM_ITEMS 50000
#define N_NODES   150000
#define DIM       64
#define NNZ       4800000
#define NEG_SLOPE 0.01f
#define NROW_BLK  ((N_NODES + 255) / 256)   // 586
#define GEMM_GRID 1184                       // 148 SMs x 8 blocks: exact wave

// Persistent scratch (allocation-free rule: __device__ globals).
__device__ float g_ego[(size_t)N_NODES * DIM];    // 38.4 MB
__device__ float g_side[(size_t)N_NODES * DIM];   // 38.4 MB
__device__ int2  g_csr[NNZ];                      // 38.4 MB {col, val bits}
__device__ int   g_count[N_NODES];
__device__ int   g_rowptr[N_NODES];
__device__ int   g_cursor[N_NODES];
__device__ int   g_blocksum[NROW_BLK];

// ---------------------------------------------------------------------------
// Init: ego = concat(user_emb, item_emb); also writes output column block 0.
// ---------------------------------------------------------------------------
__global__ void init_kernel(const float* __restrict__ ue,
                            const float* __restrict__ ie,
                            float* __restrict__ out) {
    int i = blockIdx.x * 256 + threadIdx.x;   // 0 .. N_NODES*16-1
    int node = i >> 4;
    int q    = i & 15;
    const float4* src = (node < NUM_USERS)
        ? (const float4*)(ue + (size_t)node * DIM)
        : (const float4*)(ie + (size_t)(node - NUM_USERS) * DIM);
    float4 v = src[q];
    ((float4*)(g_ego + (size_t)node * DIM))[q] = v;
    ((float4*)(out  + (size_t)node * 256))[q]  = v;
}

// ---------------------------------------------------------------------------
// CSR build, stage 0: zero per-row counts.
// ---------------------------------------------------------------------------
__global__ void zero_counts_kernel() {
    int r = blockIdx.x * 256 + threadIdx.x;
    if (r < N_NODES) g_count[r] = 0;
}

// Stage 1: histogram of destination rows.
__global__ void hist_kernel(const int* __restrict__ rows) {
    int e = blockIdx.x * 256 + threadIdx.x;
    atomicAdd(&g_count[__ldcs(rows + e)], 1);
}

// Stage 2: per-block sums of counts (586 blocks of 256).
__global__ void scan_blocksum_kernel() {
    __shared__ int swarp[8];
    int r = blockIdx.x * 256 + threadIdx.x;
    int v = (r < N_NODES) ? g_count[r] : 0;
    #pragma unroll
    for (int d = 16; d > 0; d >>= 1)
        v += __shfl_down_sync(0xffffffffu, v, d);
    int lane = threadIdx.x & 31, wid = threadIdx.x >> 5;
    if (lane == 0) swarp[wid] = v;
    __syncthreads();
    if (threadIdx.x == 0) {
        int s = 0;
        #pragma unroll
        for (int i = 0; i < 8; i++) s += swarp[i];
        g_blocksum[blockIdx.x] = s;
    }
}

// Stage 3: exclusive scan of the 586 block sums (single block).
__global__ void scan_partials_kernel() {
    __shared__ int sh[NROW_BLK];
    for (int i = threadIdx.x; i < NROW_BLK; i += blockDim.x)
        sh[i] = g_blocksum[i];
    __syncthreads();
    if (threadIdx.x == 0) {
        int run = 0;
        for (int i = 0; i < NROW_BLK; i++) { int t = sh[i]; sh[i] = run; run += t; }
    }
    __syncthreads();
    for (int i = threadIdx.x; i < NROW_BLK; i += blockDim.x)
        g_blocksum[i] = sh[i];
}

// Stage 4: block-local exclusive scan + block offset -> rowptr, cursor.
__global__ void scan_finalize_kernel() {
    __shared__ int swarp[8];
    int r = blockIdx.x * 256 + threadIdx.x;
    int lane = threadIdx.x & 31, wid = threadIdx.x >> 5;
    int v = (r < N_NODES) ? g_count[r] : 0;
    int incl = v;
    #pragma unroll
    for (int d = 1; d < 32; d <<= 1) {
        int t = __shfl_up_sync(0xffffffffu, incl, d);
        if (lane >= d) incl += t;
    }
    if (lane == 31) swarp[wid] = incl;
    __syncthreads();
    if (threadIdx.x == 0) {
        int run = 0;
        #pragma unroll
        for (int i = 0; i < 8; i++) { int t = swarp[i]; swarp[i] = run; run += t; }
    }
    __syncthreads();
    if (r < N_NODES) {
        int excl = incl - v + swarp[wid] + g_blocksum[blockIdx.x];
        g_rowptr[r] = excl;
        g_cursor[r] = excl;
    }
}

// Stage 5: scatter edges into CSR slots.
__global__ void scatter_kernel(const int*   __restrict__ rows,
                               const int*   __restrict__ cols,
                               const float* __restrict__ vals) {
    int e = blockIdx.x * 256 + threadIdx.x;
    int r = __ldcs(rows + e);
    int pos = atomicAdd(&g_cursor[r], 1);
    g_csr[pos] = make_int2(__ldcs(cols + e), __float_as_int(__ldcs(vals + e)));
}

// ---------------------------------------------------------------------------
// CSR SpMM: side[r] = sum over edges of val * ego[col]. Gather-only, no
// atomics, no zero pass. 16 threads per row, one float4 per lane. Edge
// (col,val) loads are software-prefetched one iteration ahead so the
// dependent gather address is ready ~L2-latency earlier.
// ---------------------------------------------------------------------------
__global__ __launch_bounds__(256) void spmm_csr_kernel() {
    int tid = blockIdx.x * 256 + threadIdx.x;
    int r = tid >> 4;
    int q = tid & 15;
    int start = g_rowptr[r];
    int len   = g_count[r];
    const int2* p = g_csr + start;

    float4 acc = make_float4(0.f, 0.f, 0.f, 0.f);
    if (len > 0) {
        int2 cv = __ldg(p);
        for (int i = 1; i < len; i++) {
            int2 nxt = __ldg(p + i);          // prefetch next edge
            float v = __int_as_float(cv.y);
            float4 x = ((const float4*)(g_ego + (size_t)cv.x * DIM))[q];
            acc.x += v * x.x;
            acc.y += v * x.y;
            acc.z += v * x.z;
            acc.w += v * x.w;
            cv = nxt;
        }
        float v = __int_as_float(cv.y);
        float4 x = ((const float4*)(g_ego + (size_t)cv.x * DIM))[q];
        acc.x += v * x.x;
        acc.y += v * x.y;
        acc.z += v * x.z;
        acc.w += v * x.w;
    }
    ((float4*)(g_side + (size_t)r * DIM))[q] = acc;
}

// ---------------------------------------------------------------------------
// Single-GEMM transform kernels (weight row in registers, inner loop =
// 4 broadcast LDS.128 feeding 16 FFMA -> FMA-bound).
// gc_kernel: g_ego = leaky_relu(g_side @ W^T + b)
// bi_kernel: out[:, outcol:outcol+64] = g_ego @ W^T + b
// ---------------------------------------------------------------------------
__global__ __launch_bounds__(256) void gc_kernel(
    const float* __restrict__ w, const float* __restrict__ b)
{
    __shared__ float4 sT[64][5];   // [k][node_group], 16 nodes + pad

    int tx = threadIdx.x;
    int warp = tx >> 5, lane = tx & 31;
    int o = ((warp & 1) << 5) | lane;
    int g = warp >> 1;

    float4 wr[16];
    #pragma unroll
    for (int i = 0; i < 16; i++)
        wr[i] = *(const float4*)(w + (size_t)o * DIM + i * 4);
    float bias = b[o];
    float* sTf = (float*)sT;

    for (int n0 = blockIdx.x * 16; n0 < N_NODES; n0 += gridDim.x * 16) {
        #pragma unroll
        for (int j = 0; j < 4; j++) {
            int idx = tx + j * 256;
            int nl = idx >> 6, k = idx & 63;
            sTf[k * 20 + nl] = g_side[(size_t)(n0 + nl) * DIM + k];
        }
        __syncthreads();

        float a0 = bias, a1 = bias, a2 = bias, a3 = bias;
        #pragma unroll
        for (int k4 = 0; k4 < 16; k4++) {
            float4 wv = wr[k4];
            float4 sA = sT[k4 * 4 + 0][g];
            float4 sB = sT[k4 * 4 + 1][g];
            float4 sC = sT[k4 * 4 + 2][g];
            float4 sD = sT[k4 * 4 + 3][g];
            a0 += wv.x * sA.x + wv.y * sB.x + wv.z * sC.x + wv.w * sD.x;
            a1 += wv.x * sA.y + wv.y * sB.y + wv.z * sC.y + wv.w * sD.y;
            a2 += wv.x * sA.z + wv.y * sB.z + wv.z * sC.z + wv.w * sD.z;
            a3 += wv.x * sA.w + wv.y * sB.w + wv.z * sC.w + wv.w * sD.w;
        }
        a0 = a0 > 0.f ? a0 : NEG_SLOPE * a0;
        a1 = a1 > 0.f ? a1 : NEG_SLOPE * a1;
        a2 = a2 > 0.f ? a2 : NEG_SLOPE * a2;
        a3 = a3 > 0.f ? a3 : NEG_SLOPE * a3;

        int nb = n0 + (g << 2);
        g_ego[(size_t)(nb + 0) * DIM + o] = a0;
        g_ego[(size_t)(nb + 1) * DIM + o] = a1;
        g_ego[(size_t)(nb + 2) * DIM + o] = a2;
        g_ego[(size_t)(nb + 3) * DIM + o] = a3;
        __syncthreads();   // protect sT for next iteration
    }
}

__global__ __launch_bounds__(256) void bi_kernel(
    const float* __restrict__ w, const float* __restrict__ b,
    float* __restrict__ out, int outcol)
{
    __shared__ float4 eT[64][5];

    int tx = threadIdx.x;
    int warp = tx >> 5, lane = tx & 31;
    int o = ((warp & 1) << 5) | lane;
    int g = warp >> 1;

    float4 wr[16];
    #pragma unroll
    for (int i = 0; i < 16; i++)
        wr[i] = *(const float4*)(w + (size_t)o * DIM + i * 4);
    float bias = b[o];
    float* eTf = (float*)eT;

    for (int n0 = blockIdx.x * 16; n0 < N_NODES; n0 += gridDim.x * 16) {
        #pragma unroll
        for (int j = 0; j < 4; j++) {
            int idx = tx + j * 256;
            int nl = idx >> 6, k = idx & 63;
            eTf[k * 20 + nl] = g_ego[(size_t)(n0 + nl) * DIM + k];
        }
        __syncthreads();

        float a0 = bias, a1 = bias, a2 = bias, a3 = bias;
        #pragma unroll
        for (int k4 = 0; k4 < 16; k4++) {
            float4 wv = wr[k4];
            float4 eA = eT[k4 * 4 + 0][g];
            float4 eB = eT[k4 * 4 + 1][g];
            float4 eC = eT[k4 * 4 + 2][g];
            float4 eD = eT[k4 * 4 + 3][g];
            a0 += wv.x * eA.x + wv.y * eB.x + wv.z * eC.x + wv.w * eD.x;
            a1 += wv.x * eA.y + wv.y * eB.y + wv.z * eC.y + wv.w * eD.y;
            a2 += wv.x * eA.z + wv.y * eB.z + wv.z * eC.z + wv.w * eD.z;
            a3 += wv.x * eA.w + wv.y * eB.w + wv.z * eC.w + wv.w * eD.w;
        }

        int nb = n0 + (g << 2);
        out[(size_t)(nb + 0) * 256 + outcol + o] = a0;
        out[(size_t)(nb + 1) * 256 + outcol + o] = a1;
        out[(size_t)(nb + 2) * 256 + outcol + o] = a2;
        out[(size_t)(nb + 3) * 256 + outcol + o] = a3;
        __syncthreads();   // protect eT for next iteration
    }
}

// ---------------------------------------------------------------------------
extern "C" void kernel_launch(void* const* d_in, const int* in_sizes, int n_in,
                              void* d_out, int out_size) {
    const float* user_emb = (const float*)d_in[0];
    const float* item_emb = (const float*)d_in[1];
    const float* gc_w     = (const float*)d_in[2];  // [3,64,64]
    const float* gc_b     = (const float*)d_in[3];  // [3,64]
    const float* bi_w     = (const float*)d_in[4];
    const float* bi_b     = (const float*)d_in[5];
    const int*   rows     = (const int*)d_in[6];
    const int*   cols     = (const int*)d_in[7];
    const float* vals     = (const float*)d_in[8];
    float* out = (float*)d_out;

    init_kernel<<<(N_NODES * 16) / 256, 256>>>(user_emb, item_emb, out);

    // One-time CSR build (graph is static across layers).
    zero_counts_kernel<<<NROW_BLK, 256>>>();
    hist_kernel<<<NNZ / 256, 256>>>(rows);
    scan_blocksum_kernel<<<NROW_BLK, 256>>>();
    scan_partials_kernel<<<1, 1024>>>();
    scan_finalize_kernel<<<NROW_BLK, 256>>>();
    scatter_kernel<<<NNZ / 256, 256>>>(rows, cols, vals);

    for (int l = 0; l < 3; l++) {
        spmm_csr_kernel<<<(N_NODES * 16) / 256, 256>>>();
        gc_kernel<<<GEMM_GRID, 256>>>(gc_w + (size_t)l * DIM * DIM,
                                      gc_b + (size_t)l * DIM);
        bi_kernel<<<GEMM_GRID, 256>>>(bi_w + (size_t)l * DIM * DIM,
                                      bi_b + (size_t)l * DIM,
                                      out, DIM * (l + 1));
    }
}